// round 14
// baseline (speedup 1.0000x reference)
#include <cuda_runtime.h>
#include <cuda_fp16.h>
#include <math.h>
#include <stdint.h>

// image 2048x2048 -> DWT high (stride-2, 2x2) -> 1024x1024
// pad to 1449x1449 with pad_before=212, center=724
// out[x*64 + t] = (sum_y bilinear(padded, rot_t(x,y))) / global_max, x<1448
#define MDIM  2048
#define HN    1024
#define PDIM  1449
#define PB    212
#define OUTW  1448
#define NA    64
#define CENTERF 724.0f

// rotsum touches quad indices only in [208,1240]^2; prep covers [200,1248)^2.
#define RLO   200
#define QSPAN 1048

__device__ uint2 g_h4[PDIM * PDIM];    // fp16 quad, column pairs: (v00,v10 | v01,v11)
__device__ unsigned g_maxkey;

#define PACK_F32X2(out, lo, hi) \
    asm("mov.b64 %0, {%1, %2};" : "=l"(out) : "f"(lo), "f"(hi))
#define UNPACK_F32X2(lo, hi, in) \
    asm("mov.b64 {%0, %1}, %2;" : "=f"(lo), "=f"(hi) : "l"(in))
#define FMA_F32X2(out, a, b, c) \
    asm("fma.rn.f32x2 %0, %1, %2, %3;" : "=l"(out) : "l"(a), "l"(b), "l"(c))
#define ADD_F32X2(out, a, b) \
    asm("add.rn.f32x2 %0, %1, %2;" : "=l"(out) : "l"(a), "l"(b))

// ---------------------------------------------------------------------------
// DWT high-pass value at (iy, ix); zero outside [0,1024)^2.
// ---------------------------------------------------------------------------
__device__ __forceinline__ float dwt_at(const float* __restrict__ img,
                                        int iy, int ix) {
    if ((unsigned)iy >= (unsigned)HN || (unsigned)ix >= (unsigned)HN) return 0.0f;
    const float2* r0 = (const float2*)(img + (size_t)(2 * iy) * MDIM) + ix;
    float2 a = __ldg(r0);
    float2 b = __ldg((const float2*)((const float*)r0 + MDIM));
    return -0.1384f * a.x + 0.7243f * a.y
           - 0.6038f * b.x + 0.1601f * b.y;
}

// ---------------------------------------------------------------------------
// Fused prep with shfl corner sharing: thread computes v00,v10 only;
// v01,v11 come from lane+1 (lane 31 computes its own boundary pair).
// Packs fp16 column pairs: q.x = (v00, v10), q.y = (v01, v11).
// ---------------------------------------------------------------------------
__global__ void prep_kernel(const float* __restrict__ img) {
    int lane = threadIdx.x;                 // blockDim.x == 32: warp == row
    int px = RLO + blockIdx.x * 32 + lane;
    int py = RLO + blockIdx.y * 8 + threadIdx.y;
    if (blockIdx.x == 0 && blockIdx.y == 0 && lane == 0 && threadIdx.y == 0)
        g_maxkey = 0u;
    bool live = (px < RLO + QSPAN) && (py < RLO + QSPAN);
    int iy = py - PB;
    int ix = px - PB;
    float v00 = live ? dwt_at(img, iy,     ix) : 0.0f;
    float v10 = live ? dwt_at(img, iy + 1, ix) : 0.0f;
    float v01 = __shfl_down_sync(0xffffffffu, v00, 1);
    float v11 = __shfl_down_sync(0xffffffffu, v10, 1);
    if (lane == 31 && live) {
        v01 = dwt_at(img, iy,     ix + 1);
        v11 = dwt_at(img, iy + 1, ix + 1);
    }
    if (!live) return;
    __half2 c0 = __floats2half2_rn(v00, v10);
    __half2 c1 = __floats2half2_rn(v01, v11);
    uint2 q;
    q.x = *(unsigned*)&c0;
    q.y = *(unsigned*)&c1;
    g_h4[py * PDIM + px] = q;
}

__device__ __forceinline__ unsigned float_key(float f) {
    unsigned u = __float_as_uint(f);
    return (u & 0x80000000u) ? ~u : (u | 0x80000000u);
}

// ---------------------------------------------------------------------------
// For u(Y) = a*Y + b, compute Y-intervals (widened +-2, clamped to [0,1447])
// where floor(u) falls in the nonzero window [211,1235] + 1449*(k-1), k=0,1,2.
// ---------------------------------------------------------------------------
__device__ __forceinline__ void window_intervals(float a, float b,
                                                 float* lo, float* hi) {
    const float ra = 1.0f / a;
    #pragma unroll
    for (int k = 0; k < 3; k++) {
        float wlo = 211.0f + 1449.0f * (float)(k - 1);
        float whi = 1236.0f + 1449.0f * (float)(k - 1);
        if (fabsf(a) < 1e-5f) {
            bool in = (b >= wlo - 2.0f) && (b < whi + 2.0f);
            lo[k] = in ? 0.0f : 1e9f;
            hi[k] = in ? 1447.0f : -1e9f;
        } else {
            float y0 = (wlo - b) * ra;
            float y1 = (whi - b) * ra;
            if (a < 0.0f) { float tmp = y0; y0 = y1; y1 = tmp; }
            lo[k] = fmaxf(y0 - 2.0f, 0.0f);
            hi[k] = fminf(y1 + 2.0f, 1447.0f);
        }
    }
}

// Interval-walking accumulator, y-stride 16 (phase in 0..15).
// Inner loop: packed f32x2 coord math, 1 LDG.64, half2 x-lerp, fp32 y-lerp.
__device__ __forceinline__ float accum_intervals(float s, float c,
                                                 float cxk, float syk,
                                                 int phase) {
    float xlo[3], xhi[3], ylo[3], yhi[3];
    window_intervals(s, cxk, xlo, xhi);
    window_intervals(c, syk, ylo, yhi);

    uint64_t sc, basep, step16, neg1;
    PACK_F32X2(sc, s, c);
    PACK_F32X2(basep, cxk, syk);
    { float e = 16.0f; PACK_F32X2(step16, e, e); }
    { float m = -1.0f; PACK_F32X2(neg1, m, m); }

    float acc = 0.0f;
    #pragma unroll
    for (int kx = 0; kx < 3; kx++) {
        #pragma unroll
        for (int ky = 0; ky < 3; ky++) {
            float flo = fmaxf(xlo[kx], ylo[ky]);
            float fhi = fminf(xhi[kx], yhi[ky]);
            if (flo > fhi) continue;
            const int OFFC = -(ky - 1) * 1449 * PDIM - (kx - 1) * 1449;
            int yls = (int)ceilf(flo);
            yls += (phase - yls) & 15;           // align to y == phase (mod 16)
            const int yle = (int)floorf(fhi);
            if (yls > yle) continue;
            const int n = (yle - yls) >> 4;      // iterations - 1
            uint64_t Yp;
            { float Yf = (float)yls; PACK_F32X2(Yp, Yf, Yf); }
            const uint2* __restrict__ bp = g_h4 + OFFC;
            #pragma unroll 4
            for (int i = 0; i <= n; i++) {
                uint64_t fxy, dxy, ifp;
                FMA_F32X2(fxy, sc, Yp, basep);      // (fx, fy)
                float fx, fy;
                UNPACK_F32X2(fx, fy, fxy);
                int xi = __float2int_rd(fx);
                int yi = __float2int_rd(fy);
                float xf = (float)xi, yf = (float)yi;
                PACK_F32X2(ifp, xf, yf);
                FMA_F32X2(dxy, ifp, neg1, fxy);     // (dx, dy)
                float dx, dy;
                UNPACK_F32X2(dx, dy, dxy);
                ADD_F32X2(Yp, Yp, step16);
                uint2 q = __ldg(bp + yi * PDIM + xi);
                __half2 q0 = *(__half2*)&q.x;            // (v00, v10)
                __half2 q1 = *(__half2*)&q.y;            // (v01, v11)
                __half2 tb = __hfma2(__float2half2_rn(dx),
                                     __hsub2(q1, q0), q0);  // (top, bot)
                float2 tf = __half22float2(tb);
                acc += fmaf(dy, tf.y - tf.x, tf.x);
            }
        }
    }
    return acc;
}

// ---------------------------------------------------------------------------
// Rotsum: 512 threads = 32 output columns x 16 Y-phases. Warp lane micro-tile
// shape (la x lb, la*lb=32) chosen per angle by a LINE-cost model:
// wavefronts ~ rows * lines/row:  f = (la|s|+lb|c|+1) * ((la|c|+lb|s|)*8+96).
// Shapes: 32x1, 16x2, 8x4, 4x8, 2x16.
// ---------------------------------------------------------------------------
__global__ void __launch_bounds__(512) rotsum_kernel(float* __restrict__ out) {
    const int t = blockIdx.y;
    float s, c;
    sincosf((float)t, &s, &c);
    const float as = fabsf(s), ac = fabsf(c);

    // pick lashift in {1..5} minimizing line-cost (block-uniform)
    float best = 1e30f;
    int lashift = 3;
    #pragma unroll
    for (int k = 1; k <= 5; k++) {
        float laf = (float)(1 << k);
        float lbf = (float)(32 >> k);
        float rows  = laf * as + lbf * ac + 1.0f;
        float xbyte = (laf * ac + lbf * as) * 8.0f + 96.0f;
        float cost = rows * xbyte;
        if (cost < best) { best = cost; lashift = k; }
    }
    const int la = 1 << lashift;
    const int lb = 32 >> lashift;            // lanes along phase
    const int wa = 32 >> lashift;            // warps along X
    const int washift = 5 - lashift;

    const int tid  = threadIdx.x;
    const int lane = tid & 31;
    const int w    = tid >> 5;               // 16 warps

    const int col   = ((w & (wa - 1)) << lashift) + (lane & (la - 1));
    const int phase = ((w >> washift) * lb) + (lane >> lashift);   // 0..15

    const int x = blockIdx.x * 32 + col;
    const float kx = CENTERF * (c + s - 1.0f);
    const float ky = CENTERF * (c - s - 1.0f);
    const float X = (float)x;
    const float cxk = fmaf(c, X, -kx);   // x_in = s*Y + cxk
    const float syk = fmaf(-s, X, -ky);  // y_in = c*Y + syk

    float acc = accum_intervals(s, c, cxk, syk, phase);

    __shared__ float sm[16][33];
    sm[phase][col] = acc;
    __syncthreads();

    if (tid < 32) {
        float v = sm[0][tid];
        #pragma unroll
        for (int p = 1; p < 16; p++) v += sm[p][tid];
        int xo = blockIdx.x * 32 + tid;
        float vm = v;
        if (xo < OUTW) out[(size_t)xo * NA + t] = v; else vm = -INFINITY;
        unsigned key = float_key(vm);
        #pragma unroll
        for (int o = 16; o > 0; o >>= 1) {
            unsigned other = __shfl_xor_sync(0xffffffffu, key, o);
            key = key > other ? key : other;
        }
        if (tid == 0) atomicMax(&g_maxkey, key);
    }
}

// ---------------------------------------------------------------------------
__global__ void norm_kernel(float* __restrict__ out, int n) {
    int i = blockIdx.x * blockDim.x + threadIdx.x;
    unsigned key = g_maxkey;
    unsigned u = (key & 0x80000000u) ? (key ^ 0x80000000u) : ~key;
    float m = __uint_as_float(u);
    if (i < n) out[i] = out[i] / m;
}

// ---------------------------------------------------------------------------
extern "C" void kernel_launch(void* const* d_in, const int* in_sizes, int n_in,
                              void* d_out, int out_size) {
    const float* img = (const float*)d_in[0];
    float* out = (float*)d_out;

    dim3 pb(32, 8);
    dim3 pg((QSPAN + 31) / 32, (QSPAN + 7) / 8);
    prep_kernel<<<pg, pb>>>(img);

    dim3 grid((OUTW + 31) / 32, NA);
    rotsum_kernel<<<grid, 512>>>(out);

    norm_kernel<<<(out_size + 255) / 256, 256>>>(out, out_size);
}